// round 10
// baseline (speedup 1.0000x reference)
#include <cuda_runtime.h>

#define B_DIM 8
#define CIN 512
#define COUT 3
#define WDIM 512
#define HW 65536           // 256*256
#define CONV_CLAMP 256.0f

// Staging for per-(batch, channel) coefficient triples:
//   g_m4[b*CIN+c] = (weight[0][c], weight[1][c], weight[2][c], 0) * styles[b][c]
__device__ float4 g_m4[B_DIM * CIN];

// Per-batch arrival counters (monotonic across graph replays; cohort = 64 CTAs.
// target = (start/64+1)*64, so no reset is needed -> deterministic per run).
__device__ unsigned int g_bar[B_DIM];

// ---------------------------------------------------------------------------
// Fused kernel (R7 structure, verified 155.7us) with a leaner prologue:
//   - phase-1 dot loads via float4 (4x LDG.128/lane, not 16x LDG.32)
//   - tight volatile spin (no __nanosleep quantization)
//   - NO prefetch (R9 showed it costs 2us)
// grid = (64, 8), block = 256; all 512 CTAs co-resident (4/SM x 148 = 592),
// so the per-batch spin barrier cannot deadlock.
// Phase 2 is the FROZEN R3 stream loop — byte-identical, do not restructure.
// ---------------------------------------------------------------------------
__global__ void __launch_bounds__(256)
torgb_fused_kernel(const float* __restrict__ x,
                   const float* __restrict__ w,
                   const float* __restrict__ weight,
                   const float* __restrict__ bias,
                   const float* __restrict__ affine_w,
                   const float* __restrict__ affine_b,
                   float* __restrict__ out)
{
    __shared__ float m0[CIN];
    __shared__ float m1[CIN];
    __shared__ float m2[CIN];

    const int b    = blockIdx.y;
    const int bx   = blockIdx.x;
    const int tid  = threadIdx.x;
    const int warp = tid >> 5;
    const int lane = tid & 31;

    // ---- Phase 1: compute this CTA's 8 coefficients (c = bx*8 + warp) ----
    {
        const int c = bx * 8 + warp;
        const float4* __restrict__ arow4 =
            (const float4*)(affine_w + (size_t)c * WDIM);
        const float4* __restrict__ wrow4 =
            (const float4*)(w + (size_t)b * WDIM);
        float sum = 0.0f;
#pragma unroll
        for (int j = 0; j < WDIM / 128; ++j) {          // 4 float4 per lane
            const int k = lane + 32 * j;
            const float4 av = __ldg(&arow4[k]);
            const float4 wv = __ldg(&wrow4[k]);
            sum = fmaf(av.x, wv.x, sum);
            sum = fmaf(av.y, wv.y, sum);
            sum = fmaf(av.z, wv.z, sum);
            sum = fmaf(av.w, wv.w, sum);
        }
#pragma unroll
        for (int off = 16; off > 0; off >>= 1)
            sum += __shfl_xor_sync(0xffffffffu, sum, off);

        if (lane == 0) {
            const float affine_gain = 1.0f / sqrtf((float)WDIM);
            const float cin_gain    = 1.0f / sqrtf((float)CIN);
            const float style = (sum * affine_gain + affine_b[c]) * cin_gain;
            float4 m;
            m.x = weight[0 * CIN + c] * style;
            m.y = weight[1 * CIN + c] * style;
            m.z = weight[2 * CIN + c] * style;
            m.w = 0.0f;
            g_m4[b * CIN + c] = m;
        }
    }
    __syncthreads();                 // all warps done writing g_m4

    // ---- Per-batch barrier over the 64 CTAs producing batch b ----
    if (tid == 0) {
        __threadfence();             // publish our g_m4 writes (release)
        const unsigned int start  = atomicAdd(&g_bar[b], 1u);
        const unsigned int target = (start / 64u + 1u) * 64u;
        volatile unsigned int* ctr = &g_bar[b];
        while (*ctr < target)        // tight poll: 1 thread/CTA, L2 read/iter
            ;
        __threadfence();             // acquire
    }
    __syncthreads();

    // ---- Coefficient fill for batch b (L2 via __ldcg) ----
    for (int c = tid; c < CIN; c += blockDim.x) {
        const float4 m = __ldcg(&g_m4[b * CIN + c]);
        m0[c] = m.x;
        m1[c] = m.y;
        m2[c] = m.z;
    }
    __syncthreads();

    // ---- Phase 2: the frozen streaming loop (single fixed 0..512) ----
    const int hw4 = bx * blockDim.x + tid;    // index in float4 units
    const float4* __restrict__ x4 =
        (const float4*)(x + (size_t)b * CIN * HW);

    float4 a0 = make_float4(0.f, 0.f, 0.f, 0.f);
    float4 a1 = make_float4(0.f, 0.f, 0.f, 0.f);
    float4 a2 = make_float4(0.f, 0.f, 0.f, 0.f);

#pragma unroll 4
    for (int c = 0; c < CIN; ++c) {
        const float4 xv = __ldcs(&x4[(size_t)c * (HW / 4) + hw4]);
        const float c0 = m0[c];
        const float c1 = m1[c];
        const float c2 = m2[c];
        a0.x = fmaf(xv.x, c0, a0.x); a0.y = fmaf(xv.y, c0, a0.y);
        a0.z = fmaf(xv.z, c0, a0.z); a0.w = fmaf(xv.w, c0, a0.w);
        a1.x = fmaf(xv.x, c1, a1.x); a1.y = fmaf(xv.y, c1, a1.y);
        a1.z = fmaf(xv.z, c1, a1.z); a1.w = fmaf(xv.w, c1, a1.w);
        a2.x = fmaf(xv.x, c2, a2.x); a2.y = fmaf(xv.y, c2, a2.y);
        a2.z = fmaf(xv.z, c2, a2.z); a2.w = fmaf(xv.w, c2, a2.w);
    }

    const float bv0 = bias[0];
    const float bv1 = bias[1];
    const float bv2 = bias[2];

#define CLAMP1(v) fminf(fmaxf((v), -CONV_CLAMP), CONV_CLAMP)
    float4 o0 = make_float4(CLAMP1(a0.x + bv0), CLAMP1(a0.y + bv0),
                            CLAMP1(a0.z + bv0), CLAMP1(a0.w + bv0));
    float4 o1 = make_float4(CLAMP1(a1.x + bv1), CLAMP1(a1.y + bv1),
                            CLAMP1(a1.z + bv1), CLAMP1(a1.w + bv1));
    float4 o2 = make_float4(CLAMP1(a2.x + bv2), CLAMP1(a2.y + bv2),
                            CLAMP1(a2.z + bv2), CLAMP1(a2.w + bv2));
#undef CLAMP1

    float4* __restrict__ out4 = (float4*)out;
    const size_t obase = (size_t)b * COUT * (HW / 4);
    __stcs(&out4[obase + 0 * (HW / 4) + hw4], o0);
    __stcs(&out4[obase + 1 * (HW / 4) + hw4], o1);
    __stcs(&out4[obase + 2 * (HW / 4) + hw4], o2);
}

// ---------------------------------------------------------------------------
// Launch
//   d_in[0] = x        [B, CIN, H, W]  f32
//   d_in[1] = w        [B, WDIM]       f32
//   d_in[2] = weight   [COUT, CIN,1,1] f32
//   d_in[3] = bias     [COUT]          f32
//   d_in[4] = affine_w [CIN, WDIM]     f32
//   d_in[5] = affine_b [CIN]           f32
// ---------------------------------------------------------------------------
extern "C" void kernel_launch(void* const* d_in, const int* in_sizes, int n_in,
                              void* d_out, int out_size)
{
    const float* x        = (const float*)d_in[0];
    const float* w        = (const float*)d_in[1];
    const float* weight   = (const float*)d_in[2];
    const float* bias     = (const float*)d_in[3];
    const float* affine_w = (const float*)d_in[4];
    const float* affine_b = (const float*)d_in[5];
    float* out = (float*)d_out;

    dim3 cgrid(HW / 4 / 256, B_DIM);
    torgb_fused_kernel<<<cgrid, 256>>>(x, w, weight, bias,
                                       affine_w, affine_b, out);
}

// round 11
// speedup vs baseline: 1.0056x; 1.0056x over previous
#include <cuda_runtime.h>

#define B_DIM 8
#define CIN 512
#define COUT 3
#define WDIM 512
#define HW 65536           // 256*256
#define CONV_CLAMP 256.0f

// Staging for per-(batch, channel) coefficient triples:
//   g_m4[b*CIN+c] = (weight[0][c], weight[1][c], weight[2][c], 0) * styles[b][c]
__device__ float4 g_m4[B_DIM * CIN];

// Per-batch arrival counters (monotonic across graph replays; cohort = 64 CTAs.
// target = (start/64+1)*64, so no reset is needed -> deterministic per run).
__device__ unsigned int g_bar[B_DIM];

// ---------------------------------------------------------------------------
// Fused kernel = EXACT R7 structure (verified 155.7us kernel) + one change:
// the first 4 c-rows of the stream are loaded into registers BETWEEN the
// barrier arrive and the wait. Real work (not prefetch), issued by all 8
// warps -> DRAM stays busy through the ~3us barrier window. Main loop is a
// single fixed-bound c=4..512 loop with the frozen R3 body.
// grid = (64, 8), block = 256; all 512 CTAs co-resident -> no deadlock.
// ---------------------------------------------------------------------------
__global__ void __launch_bounds__(256)
torgb_fused_kernel(const float* __restrict__ x,
                   const float* __restrict__ w,
                   const float* __restrict__ weight,
                   const float* __restrict__ bias,
                   const float* __restrict__ affine_w,
                   const float* __restrict__ affine_b,
                   float* __restrict__ out)
{
    __shared__ float m0[CIN];
    __shared__ float m1[CIN];
    __shared__ float m2[CIN];

    const int b    = blockIdx.y;
    const int bx   = blockIdx.x;
    const int tid  = threadIdx.x;
    const int warp = tid >> 5;
    const int lane = tid & 31;

    const int hw4 = bx * blockDim.x + tid;    // index in float4 units
    const float4* __restrict__ x4 =
        (const float4*)(x + (size_t)b * CIN * HW);

    // ---- Phase 1: compute this CTA's 8 coefficients (c = bx*8 + warp) ----
    {
        const int c = bx * 8 + warp;
        const float* __restrict__ arow = affine_w + (size_t)c * WDIM;
        const float* __restrict__ wrow = w + (size_t)b * WDIM;
        float sum = 0.0f;
#pragma unroll
        for (int j = 0; j < WDIM / 32; ++j) {
            const int k = lane + 32 * j;
            sum = fmaf(__ldg(&arow[k]), __ldg(&wrow[k]), sum);
        }
#pragma unroll
        for (int off = 16; off > 0; off >>= 1)
            sum += __shfl_xor_sync(0xffffffffu, sum, off);

        if (lane == 0) {
            const float affine_gain = 1.0f / sqrtf((float)WDIM);
            const float cin_gain    = 1.0f / sqrtf((float)CIN);
            const float style = (sum * affine_gain + affine_b[c]) * cin_gain;
            float4 m;
            m.x = weight[0 * CIN + c] * style;
            m.y = weight[1 * CIN + c] * style;
            m.z = weight[2 * CIN + c] * style;
            m.w = 0.0f;
            g_m4[b * CIN + c] = m;
        }
    }
    __syncthreads();                 // all warps done writing g_m4

    // ---- Early arrive (release); no wait yet ----
    unsigned int target = 0;
    if (tid == 0) {
        __threadfence();             // publish our g_m4 writes
        const unsigned int start = atomicAdd(&g_bar[b], 1u);
        target = (start / 64u + 1u) * 64u;
    }

    // ---- Preload first 4 c-rows into registers: real stream work issued
    //      during the barrier window (8MB chip-wide DRAM activity) ----
    const float4 p0 = __ldcs(&x4[(size_t)0 * (HW / 4) + hw4]);
    const float4 p1 = __ldcs(&x4[(size_t)1 * (HW / 4) + hw4]);
    const float4 p2 = __ldcs(&x4[(size_t)2 * (HW / 4) + hw4]);
    const float4 p3 = __ldcs(&x4[(size_t)3 * (HW / 4) + hw4]);

    // ---- Wait for the batch cohort (64 CTAs) ----
    if (tid == 0) {
        volatile unsigned int* ctr = &g_bar[b];
        while (*ctr < target)
            __nanosleep(32);
        __threadfence();             // acquire
    }
    __syncthreads();

    // ---- Coefficient fill for batch b (L2 via __ldcg) ----
    for (int c = tid; c < CIN; c += blockDim.x) {
        const float4 m = __ldcg(&g_m4[b * CIN + c]);
        m0[c] = m.x;
        m1[c] = m.y;
        m2[c] = m.z;
    }
    __syncthreads();

    float4 a0 = make_float4(0.f, 0.f, 0.f, 0.f);
    float4 a1 = make_float4(0.f, 0.f, 0.f, 0.f);
    float4 a2 = make_float4(0.f, 0.f, 0.f, 0.f);

    // ---- Peeled c = 0..3 consuming the preloaded registers ----
#define FMA3(xv, c)                                                       \
    {                                                                     \
        const float c0 = m0[(c)];                                         \
        const float c1 = m1[(c)];                                         \
        const float c2 = m2[(c)];                                         \
        a0.x = fmaf((xv).x, c0, a0.x); a0.y = fmaf((xv).y, c0, a0.y);     \
        a0.z = fmaf((xv).z, c0, a0.z); a0.w = fmaf((xv).w, c0, a0.w);     \
        a1.x = fmaf((xv).x, c1, a1.x); a1.y = fmaf((xv).y, c1, a1.y);     \
        a1.z = fmaf((xv).z, c1, a1.z); a1.w = fmaf((xv).w, c1, a1.w);     \
        a2.x = fmaf((xv).x, c2, a2.x); a2.y = fmaf((xv).y, c2, a2.y);     \
        a2.z = fmaf((xv).z, c2, a2.z); a2.w = fmaf((xv).w, c2, a2.w);     \
    }
    FMA3(p0, 0)
    FMA3(p1, 1)
    FMA3(p2, 2)
    FMA3(p3, 3)

    // ---- Main stream: frozen R3 body, single fixed-bound loop c=4..512 ----
#pragma unroll 4
    for (int c = 4; c < CIN; ++c) {
        const float4 xv = __ldcs(&x4[(size_t)c * (HW / 4) + hw4]);
        FMA3(xv, c)
    }
#undef FMA3

    const float bv0 = bias[0];
    const float bv1 = bias[1];
    const float bv2 = bias[2];

#define CLAMP1(v) fminf(fmaxf((v), -CONV_CLAMP), CONV_CLAMP)
    float4 o0 = make_float4(CLAMP1(a0.x + bv0), CLAMP1(a0.y + bv0),
                            CLAMP1(a0.z + bv0), CLAMP1(a0.w + bv0));
    float4 o1 = make_float4(CLAMP1(a1.x + bv1), CLAMP1(a1.y + bv1),
                            CLAMP1(a1.z + bv1), CLAMP1(a1.w + bv1));
    float4 o2 = make_float4(CLAMP1(a2.x + bv2), CLAMP1(a2.y + bv2),
                            CLAMP1(a2.z + bv2), CLAMP1(a2.w + bv2));
#undef CLAMP1

    float4* __restrict__ out4 = (float4*)out;
    const size_t obase = (size_t)b * COUT * (HW / 4);
    __stcs(&out4[obase + 0 * (HW / 4) + hw4], o0);
    __stcs(&out4[obase + 1 * (HW / 4) + hw4], o1);
    __stcs(&out4[obase + 2 * (HW / 4) + hw4], o2);
}

// ---------------------------------------------------------------------------
// Launch
//   d_in[0] = x        [B, CIN, H, W]  f32
//   d_in[1] = w        [B, WDIM]       f32
//   d_in[2] = weight   [COUT, CIN,1,1] f32
//   d_in[3] = bias     [COUT]          f32
//   d_in[4] = affine_w [CIN, WDIM]     f32
//   d_in[5] = affine_b [CIN]           f32
// ---------------------------------------------------------------------------
extern "C" void kernel_launch(void* const* d_in, const int* in_sizes, int n_in,
                              void* d_out, int out_size)
{
    const float* x        = (const float*)d_in[0];
    const float* w        = (const float*)d_in[1];
    const float* weight   = (const float*)d_in[2];
    const float* bias     = (const float*)d_in[3];
    const float* affine_w = (const float*)d_in[4];
    const float* affine_b = (const float*)d_in[5];
    float* out = (float*)d_out;

    dim3 cgrid(HW / 4 / 256, B_DIM);
    torgb_fused_kernel<<<cgrid, 256>>>(x, w, weight, bias,
                                       affine_w, affine_b, out);
}